// round 12
// baseline (speedup 1.0000x reference)
#include <cuda_runtime.h>
#include <stdint.h>

#define BB    16
#define DD    512
#define NN    2048
#define NSAMP 15
#define TOPK  16
typedef unsigned long long u64;

// ---------------- scratch (__device__ globals; no allocation) ----------------
__device__ float g_logits[(size_t)BB * NN * NN];   // 256 MB
__device__ float g_colsum[BB * NN];
__device__ float g_topval[(size_t)BB * NN * TOPK];
__device__ int   g_topcol[(size_t)BB * NN * TOPK];
__device__ uint2 g_Asp[(size_t)BB * DD * NN];      // 134 MB (hi,lo) tf32
__device__ uint2 g_Bsp[(size_t)BB * DD * NN];      // 134 MB

// ---------------- helpers ----------------
__device__ __forceinline__ uint32_t smem_u32(const void* p) {
    uint32_t a;
    asm("{ .reg .u64 t; cvta.to.shared.u64 t, %1; cvt.u32.u64 %0, t; }" : "=r"(a) : "l"(p));
    return a;
}
__device__ __forceinline__ void cp16(uint32_t dst, const void* src) {
    asm volatile("cp.async.cg.shared.global [%0], [%1], 16;" :: "r"(dst), "l"(src));
}
#define CP_COMMIT() asm volatile("cp.async.commit_group;" ::: "memory")

__device__ __forceinline__ uint2 split_tf32(float x) {
    uint32_t h, l;
    asm("cvt.rna.tf32.f32 %0, %1;" : "=r"(h) : "f"(x));
    float r = x - __uint_as_float(h);
    asm("cvt.rna.tf32.f32 %0, %1;" : "=r"(l) : "f"(r));
    return make_uint2(h, l);
}

#define MMA8(d, a, b)                                                              \
    asm volatile("mma.sync.aligned.m16n8k8.row.col.f32.tf32.tf32.f32 "             \
        "{%0,%1,%2,%3}, {%4,%5,%6,%7}, {%8,%9}, {%0,%1,%2,%3};"                    \
        : "+f"((d)[0]), "+f"((d)[1]), "+f"((d)[2]), "+f"((d)[3])                   \
        : "r"((a)[0]), "r"((a)[1]), "r"((a)[2]), "r"((a)[3]),                      \
          "r"((b)[0]), "r"((b)[1]))

__device__ __forceinline__ float fast_exp(float x) {
    float t = fmaxf(x * 1.4426950408889634f, -120.0f);
    float r = rintf(t);
    float f = t - r;
    float p = 1.5403530e-4f;
    p = fmaf(p, f, 1.3333558e-3f);
    p = fmaf(p, f, 9.6181291e-3f);
    p = fmaf(p, f, 5.5504109e-2f);
    p = fmaf(p, f, 2.4022651e-1f);
    p = fmaf(p, f, 6.9314718e-1f);
    p = fmaf(p, f, 1.0f);
    return __int_as_float(__float_as_int(p) + ((int)r << 23));
}

__global__ void k_zero_colsum() {
    int i = blockIdx.x * 256 + threadIdx.x;
    if (i < BB * NN) g_colsum[i] = 0.0f;
}

// ---------------------------------------------------------------------------
// Split precompute: fp32 -> interleaved (hi,lo) tf32 pairs, float4-vectorized.
// ---------------------------------------------------------------------------
__global__ __launch_bounds__(256) void k_split(const float* __restrict__ se,
                                               const float* __restrict__ te) {
    size_t i = (size_t)blockIdx.x * 256 + threadIdx.x;
    const float4* src = (const float4*)(blockIdx.y ? te : se);
    uint4* dst = (uint4*)(blockIdx.y ? g_Bsp : g_Asp);
    float4 x = src[i];
    uint2 s0 = split_tf32(x.x), s1 = split_tf32(x.y);
    uint2 s2 = split_tf32(x.z), s3 = split_tf32(x.w);
    dst[i * 2 + 0] = make_uint4(s0.x, s0.y, s1.x, s1.y);
    dst[i * 2 + 1] = make_uint4(s2.x, s2.y, s3.x, s3.y);
}

// ---------------------------------------------------------------------------
// GEMM via mma.sync tf32 (3xTF32), pre-split (hi,lo) operands.  (R10, kept)
// CTA tile 256(m) x 128(n), 256 threads = 8 warps (4m x 2n) of 64x64.
// ---------------------------------------------------------------------------
#define PADA 260
#define PADB 132
#define A_TILE_U (32 * PADA)
#define B_TILE_U (32 * PADB)
#define STAGE_U  (A_TILE_U + B_TILE_U)

__global__ __launch_bounds__(256, 1) void k_gemm_mma(int dummy) {
    extern __shared__ uint2 sm[];
    const int b = blockIdx.z;
    const int m0 = blockIdx.y * 256;
    const int n0 = blockIdx.x * 128;
    const uint2* Ah = g_Asp + (size_t)b * DD * NN;
    const uint2* Bh = g_Bsp + (size_t)b * DD * NN;

    const int tid = threadIdx.x;
    const int lane = tid & 31;
    const int wid = tid >> 5;
    const int wm = wid & 3;
    const int wn = wid >> 2;

    float acc[4][8][4];
#pragma unroll
    for (int i = 0; i < 4; i++)
#pragma unroll
        for (int j = 0; j < 8; j++)
#pragma unroll
            for (int q = 0; q < 4; q++) acc[i][j][q] = 0.0f;

    auto load_stage = [&](int kt, int s) {
        uint2* dA = sm + (size_t)s * STAGE_U;
        uint2* dB = dA + A_TILE_U;
#pragma unroll
        for (int i = 0; i < 16; i++) {
            int u = tid + i * 256;
            int k = u >> 7, c = u & 127;
            cp16(smem_u32(dA + k * PADA + c * 2),
                 Ah + (size_t)(kt * 32 + k) * NN + m0 + c * 2);
        }
#pragma unroll
        for (int i = 0; i < 8; i++) {
            int u = tid + i * 256;
            int k = u >> 6, c = u & 63;
            cp16(smem_u32(dB + k * PADB + c * 2),
                 Bh + (size_t)(kt * 32 + k) * NN + n0 + c * 2);
        }
        CP_COMMIT();
    };

    load_stage(0, 0);

    for (int kt = 0; kt < 16; kt++) {
        if (kt + 1 < 16) {
            load_stage(kt + 1, (kt + 1) & 1);
            asm volatile("cp.async.wait_group 1;" ::: "memory");
        } else {
            asm volatile("cp.async.wait_group 0;" ::: "memory");
        }
        __syncthreads();

        const uint2* As = sm + (size_t)(kt & 1) * STAGE_U;
        const uint2* Bs = As + A_TILE_U;

#pragma unroll
        for (int kk = 0; kk < 4; kk++) {
            const int kb = kk * 8 + (lane & 3);
            uint32_t ah[4][4], al[4][4], bh[8][2], bl[8][2];
#pragma unroll
            for (int mt = 0; mt < 4; mt++) {
                int m = wm * 64 + mt * 16 + (lane >> 2);
                uint2 x0 = As[kb * PADA + m];
                uint2 x1 = As[kb * PADA + m + 8];
                uint2 x2 = As[(kb + 4) * PADA + m];
                uint2 x3 = As[(kb + 4) * PADA + m + 8];
                ah[mt][0] = x0.x; al[mt][0] = x0.y;
                ah[mt][1] = x1.x; al[mt][1] = x1.y;
                ah[mt][2] = x2.x; al[mt][2] = x2.y;
                ah[mt][3] = x3.x; al[mt][3] = x3.y;
            }
#pragma unroll
            for (int nt = 0; nt < 8; nt++) {
                int n = wn * 64 + nt * 8 + (lane >> 2);
                uint2 y0 = Bs[kb * PADB + n];
                uint2 y1 = Bs[(kb + 4) * PADB + n];
                bh[nt][0] = y0.x; bl[nt][0] = y0.y;
                bh[nt][1] = y1.x; bl[nt][1] = y1.y;
            }
#pragma unroll
            for (int mt = 0; mt < 4; mt++)
#pragma unroll
                for (int nt = 0; nt < 8; nt++) {
                    MMA8(acc[mt][nt], ah[mt], bh[nt]);
                    MMA8(acc[mt][nt], ah[mt], bl[nt]);
                    MMA8(acc[mt][nt], al[mt], bh[nt]);
                }
        }
        __syncthreads();
    }

    const float scl = 0.04419417382415922f;   // 1/sqrt(512)
    float* C = g_logits + (size_t)b * NN * NN;
#pragma unroll
    for (int mt = 0; mt < 4; mt++) {
        int row = m0 + wm * 64 + mt * 16 + (lane >> 2);
#pragma unroll
        for (int nt = 0; nt < 8; nt++) {
            int col = n0 + wn * 64 + nt * 8 + 2 * (lane & 3);
            float2 lo = make_float2(acc[mt][nt][0] * scl, acc[mt][nt][1] * scl);
            float2 hi = make_float2(acc[mt][nt][2] * scl, acc[mt][nt][3] * scl);
            *(float2*)(C + (size_t)row * NN + col) = lo;
            *(float2*)(C + (size_t)(row + 8) * NN + col) = hi;
        }
    }
}

// ---------------------------------------------------------------------------
// Softmax + colsum + per-row top-16 — EXACT R2 version (fastest measured).
// Block = 32 rows of one batch, 256 threads (8 cols per thread per row).
// ---------------------------------------------------------------------------
__global__ __launch_bounds__(256) void k_softmax_top() {
    const int b = blockIdx.y;
    const int row0 = blockIdx.x * 32;
    const int tid = threadIdx.x;
    const int lane = tid & 31;
    const int wid = tid >> 5;

    __shared__ float colAcc[NN];
    __shared__ float s_red[8];
    __shared__ u64 s_k[8];

    for (int i = tid; i < NN; i += 256) colAcc[i] = 0.0f;
    __syncthreads();

    for (int r = 0; r < 32; r++) {
        const int row = row0 + r;
        const float* L = g_logits + ((size_t)b * NN + row) * NN;
        float v[8];
#pragma unroll
        for (int k = 0; k < 8; k++) v[k] = L[tid + k * 256];

        float m = v[0];
#pragma unroll
        for (int k = 1; k < 8; k++) m = fmaxf(m, v[k]);
#pragma unroll
        for (int off = 16; off; off >>= 1)
            m = fmaxf(m, __shfl_xor_sync(0xFFFFFFFFu, m, off));
        if (lane == 0) s_red[wid] = m;
        __syncthreads();
        float bm = s_red[0];
#pragma unroll
        for (int w = 1; w < 8; w++) bm = fmaxf(bm, s_red[w]);
        __syncthreads();

        float sum = 0.0f;
#pragma unroll
        for (int k = 0; k < 8; k++) { v[k] = fast_exp(v[k] - bm); sum += v[k]; }
#pragma unroll
        for (int off = 16; off; off >>= 1)
            sum += __shfl_xor_sync(0xFFFFFFFFu, sum, off);
        if (lane == 0) s_red[wid] = sum;
        __syncthreads();
        float Z = 0.0f;
#pragma unroll
        for (int w = 0; w < 8; w++) Z += s_red[w];
        float inv = 1.0f / Z;
#pragma unroll
        for (int k = 0; k < 8; k++) { v[k] *= inv; colAcc[tid + k * 256] += v[k]; }

        unsigned msk = 0;
        for (int it = 0; it < TOPK; it++) {
            u64 best = 0ull;
#pragma unroll
            for (int k = 0; k < 8; k++) {
                if (msk & (1u << k)) continue;
                unsigned col = (unsigned)tid + (unsigned)k * 256u;
                u64 key = ((u64)__float_as_uint(v[k]) << 32) | (u64)(0xFFFFFFFFu - col);
                if (key > best) best = key;
            }
#pragma unroll
            for (int off = 16; off; off >>= 1) {
                u64 o = __shfl_xor_sync(0xFFFFFFFFu, best, off);
                if (o > best) best = o;
            }
            __syncthreads();
            if (lane == 0) s_k[wid] = best;
            __syncthreads();
            u64 g = s_k[0];
#pragma unroll
            for (int w = 1; w < 8; w++) if (s_k[w] > g) g = s_k[w];
            unsigned col = 0xFFFFFFFFu - (unsigned)(g & 0xFFFFFFFFu);
            if ((col & 255u) == (unsigned)tid) msk |= 1u << (col >> 8);
            if (tid == 0) {
                g_topval[((size_t)b * NN + row) * TOPK + it] = __uint_as_float((unsigned)(g >> 32));
                g_topcol[((size_t)b * NN + row) * TOPK + it] = (int)col;
            }
        }
        __syncthreads();
    }

    for (int i = tid; i < NN; i += 256)
        atomicAdd(&g_colsum[b * NN + i], colAcc[i]);
}

// ---------------------------------------------------------------------------
// Tail: smem-cached greedy matching + Kabsch (fp32 Jacobi) + translation
// ---------------------------------------------------------------------------
__global__ __launch_bounds__(256) void k_match_tail(const float* __restrict__ src,
                                                    const float* __restrict__ tgt,
                                                    float* __restrict__ out) {
    const int b = blockIdx.x;
    const int tid = threadIdx.x;
    const int lane = tid & 31;
    const int wid = tid >> 5;

    __shared__ u64 curk[NN];
    __shared__ unsigned short ptrs[NN];
    __shared__ unsigned char usedc[NN];
    __shared__ u64 wred[8];
    __shared__ float sredf[8];
    __shared__ float sums[6];
    __shared__ int selR[NSAMP], selC[NSAMP];

    float a[6] = {0, 0, 0, 0, 0, 0};
    for (int n = tid; n < NN; n += 256) {
        const float* sp = src + ((size_t)b * NN + n) * 3;
        a[0] += sp[0]; a[1] += sp[1]; a[2] += sp[2];
        float w = g_colsum[b * NN + n];
        const float* tp = tgt + ((size_t)b * NN + n) * 3;
        a[3] += tp[0] * w; a[4] += tp[1] * w; a[5] += tp[2] * w;
    }
#pragma unroll
    for (int q = 0; q < 6; q++) {
        float v = a[q];
#pragma unroll
        for (int off = 16; off; off >>= 1) v += __shfl_xor_sync(0xFFFFFFFFu, v, off);
        if (lane == 0) sredf[wid] = v;
        __syncthreads();
        if (tid == 0) {
            float s = 0;
#pragma unroll
            for (int w = 0; w < 8; w++) s += sredf[w];
            sums[q] = s;
        }
        __syncthreads();
    }

    for (int r = tid; r < NN; r += 256) {
        usedc[r] = 0;
        ptrs[r] = 0;
        float v = g_topval[((size_t)b * NN + r) * TOPK];
        int c = g_topcol[((size_t)b * NN + r) * TOPK];
        curk[r] = ((u64)__float_as_uint(v) << 32) | ((u64)(2047 - r) << 11) | (u64)c;
    }
    __syncthreads();

    for (int it = 0; it < NSAMP; it++) {
        u64 best = 0ull;
#pragma unroll
        for (int k = 0; k < 8; k++) {
            u64 x = curk[tid + k * 256];
            if (x > best) best = x;
        }
#pragma unroll
        for (int off = 16; off; off >>= 1) {
            u64 o = __shfl_xor_sync(0xFFFFFFFFu, best, off);
            if (o > best) best = o;
        }
        if (lane == 0) wred[wid] = best;
        __syncthreads();
        if (tid == 0) {
            u64 g = wred[0];
#pragma unroll
            for (int w = 1; w < 8; w++) if (wred[w] > g) g = wred[w];
            int r = 2047 - (int)((g >> 11) & 0x7FF);
            int c = (int)(g & 0x7FF);
            selR[it] = r; selC[it] = c;
            usedc[c] = 1;
            curk[r] = 0ull;
        }
        __syncthreads();
        int cstar = selC[it];
#pragma unroll
        for (int k = 0; k < 8; k++) {
            int r = tid + k * 256;
            u64 x = curk[r];
            if (x && (int)(x & 0x7FF) == cstar) {
                const int* tc = &g_topcol[((size_t)b * NN + r) * TOPK];
                const float* tv = &g_topval[((size_t)b * NN + r) * TOPK];
                int p = ptrs[r];
                do { p++; } while (usedc[tc[p]]);
                ptrs[r] = (unsigned short)p;
                curk[r] = ((u64)__float_as_uint(tv[p]) << 32) |
                          ((u64)(2047 - r) << 11) | (u64)tc[p];
            }
        }
        __syncthreads();
    }

    if (tid != 0) return;

    float sp[NSAMP][3], tp[NSAMP][3];
    float ms[3] = {0, 0, 0}, mt[3] = {0, 0, 0};
    for (int s = 0; s < NSAMP; s++) {
        const float* ps = src + ((size_t)b * NN + selR[s]) * 3;
        const float* pt = tgt + ((size_t)b * NN + selC[s]) * 3;
        for (int i = 0; i < 3; i++) {
            sp[s][i] = ps[i]; ms[i] += sp[s][i];
            tp[s][i] = pt[i]; mt[i] += tp[s][i];
        }
    }
    for (int i = 0; i < 3; i++) { ms[i] *= (1.0f / NSAMP); mt[i] *= (1.0f / NSAMP); }

    float Hm[3][3] = {{0,0,0},{0,0,0},{0,0,0}};
    for (int s = 0; s < NSAMP; s++)
        for (int i = 0; i < 3; i++)
            for (int j = 0; j < 3; j++)
                Hm[i][j] += (sp[s][i] - ms[i]) * (tp[s][j] - mt[j]);

    float Aq[3][3];
    for (int i = 0; i < 3; i++)
        for (int j = 0; j < 3; j++) {
            float acc = 0;
            for (int k = 0; k < 3; k++) acc += Hm[k][i] * Hm[k][j];
            Aq[i][j] = acc;
        }
    float Vv[3][3] = {{1,0,0},{0,1,0},{0,0,1}};
    const int prs[3][2] = {{0,1},{0,2},{1,2}};
    for (int rot = 0; rot < 24; rot++) {
        int p = prs[rot % 3][0], q = prs[rot % 3][1];
        float apq = Aq[p][q];
        if (fabsf(apq) < 1e-30f) continue;
        float theta = (Aq[q][q] - Aq[p][p]) / (2.0f * apq);
        float tt = (theta >= 0 ? 1.0f : -1.0f) / (fabsf(theta) + sqrtf(theta * theta + 1.0f));
        float c = rsqrtf(tt * tt + 1.0f);
        float s = tt * c;
        for (int k = 0; k < 3; k++) {
            float akp = Aq[k][p], akq = Aq[k][q];
            Aq[k][p] = c * akp - s * akq;
            Aq[k][q] = s * akp + c * akq;
        }
        for (int k = 0; k < 3; k++) {
            float apk = Aq[p][k], aqk = Aq[q][k];
            Aq[p][k] = c * apk - s * aqk;
            Aq[q][k] = s * apk + c * aqk;
        }
        for (int k = 0; k < 3; k++) {
            float vkp = Vv[k][p], vkq = Vv[k][q];
            Vv[k][p] = c * vkp - s * vkq;
            Vv[k][q] = s * vkp + c * vkq;
        }
    }
    float lam[3] = {Aq[0][0], Aq[1][1], Aq[2][2]};
    int ord[3] = {0, 1, 2};
    for (int i = 0; i < 2; i++)
        for (int j = i + 1; j < 3; j++)
            if (lam[ord[j]] > lam[ord[i]]) { int t0 = ord[i]; ord[i] = ord[j]; ord[j] = t0; }

    float Vs[3][3], U[3][3];
    for (int i = 0; i < 3; i++) {
        float sg = sqrtf(fmaxf(lam[ord[i]], 1e-30f));
        for (int k = 0; k < 3; k++) Vs[k][i] = Vv[k][ord[i]];
        for (int k = 0; k < 3; k++) {
            float acc = 0;
            for (int j = 0; j < 3; j++) acc += Hm[k][j] * Vs[j][i];
            U[k][i] = acc / sg;
        }
    }
    float Rr[3][3];
    for (int i = 0; i < 3; i++)
        for (int j = 0; j < 3; j++) {
            float acc = 0;
            for (int k = 0; k < 3; k++) acc += Vs[i][k] * U[j][k];
            Rr[i][j] = acc;
        }
    float det = Rr[0][0] * (Rr[1][1] * Rr[2][2] - Rr[1][2] * Rr[2][1])
              - Rr[0][1] * (Rr[1][0] * Rr[2][2] - Rr[1][2] * Rr[2][0])
              + Rr[0][2] * (Rr[1][0] * Rr[2][1] - Rr[1][1] * Rr[2][0]);
    if (det < 0) {
        for (int k = 0; k < 3; k++) Vs[k][2] = -Vs[k][2];
        for (int i = 0; i < 3; i++)
            for (int j = 0; j < 3; j++) {
                float acc = 0;
                for (int k = 0; k < 3; k++) acc += Vs[i][k] * U[j][k];
                Rr[i][j] = acc;
            }
    }

    float msrc[3] = {sums[0] / (float)NN, sums[1] / (float)NN, sums[2] / (float)NN};
    float corr[3] = {sums[3] / (float)NN, sums[4] / (float)NN, sums[5] / (float)NN};
    for (int i = 0; i < 3; i++)
        for (int j = 0; j < 3; j++)
            out[b * 9 + i * 3 + j] = Rr[i][j];
    for (int i = 0; i < 3; i++) {
        float ti = -(Rr[i][0] * msrc[0] + Rr[i][1] * msrc[1] + Rr[i][2] * msrc[2]) + corr[i];
        out[BB * 9 + b * 3 + i] = ti;
    }
}

// ---------------------------------------------------------------------------
extern "C" void kernel_launch(void* const* d_in, const int* in_sizes, int n_in,
                              void* d_out, int out_size) {
    const float* se  = (const float*)d_in[0];
    const float* te  = (const float*)d_in[1];
    const float* src = (const float*)d_in[2];
    const float* tgt = (const float*)d_in[3];
    float* out = (float*)d_out;

    const int smem_bytes = 2 * STAGE_U * (int)sizeof(uint2);   // 200704
    cudaFuncSetAttribute(k_gemm_mma, cudaFuncAttributeMaxDynamicSharedMemorySize,
                         smem_bytes);

    k_zero_colsum<<<(BB * NN + 255) / 256, 256>>>();
    k_split<<<dim3(16384, 2), 256>>>(se, te);
    k_gemm_mma<<<dim3(16, 8, BB), 256, smem_bytes>>>(0);
    k_softmax_top<<<dim3(NN / 32, BB), 256>>>();
    k_match_tail<<<BB, 256>>>(src, tgt, out);
}

// round 13
// speedup vs baseline: 1.6532x; 1.6532x over previous
#include <cuda_runtime.h>
#include <stdint.h>

#define BB    16
#define DD    512
#define NN    2048
#define NSAMP 15
typedef unsigned long long u64;

// ---------------- scratch (__device__ globals; no allocation) ----------------
__device__ float g_logits[(size_t)BB * NN * NN];   // 256 MB
__device__ float g_colsum[BB * NN];
__device__ float g_bm[BB * NN];      // per-row max logit
__device__ float g_inv[BB * NN];     // per-row 1/Z
__device__ int   g_t1col[BB * NN];   // per-row argmax col

// ---------------- helpers ----------------
__device__ __forceinline__ uint32_t smem_u32(const void* p) {
    uint32_t a;
    asm("{ .reg .u64 t; cvta.to.shared.u64 t, %1; cvt.u32.u64 %0, t; }" : "=r"(a) : "l"(p));
    return a;
}
__device__ __forceinline__ void cp16(uint32_t dst, const void* src) {
    asm volatile("cp.async.cg.shared.global [%0], [%1], 16;" :: "r"(dst), "l"(src));
}
#define CP_COMMIT() asm volatile("cp.async.commit_group;" ::: "memory")

__device__ __forceinline__ void split_tf32(float x, uint32_t& hi, uint32_t& lo) {
    uint32_t h, l;
    asm("cvt.rna.tf32.f32 %0, %1;" : "=r"(h) : "f"(x));
    float r = x - __uint_as_float(h);
    asm("cvt.rna.tf32.f32 %0, %1;" : "=r"(l) : "f"(r));
    hi = h; lo = l;
}

#define MMA8(d, a, b)                                                              \
    asm volatile("mma.sync.aligned.m16n8k8.row.col.f32.tf32.tf32.f32 "             \
        "{%0,%1,%2,%3}, {%4,%5,%6,%7}, {%8,%9}, {%0,%1,%2,%3};"                    \
        : "+f"((d)[0]), "+f"((d)[1]), "+f"((d)[2]), "+f"((d)[3])                   \
        : "r"((a)[0]), "r"((a)[1]), "r"((a)[2]), "r"((a)[3]),                      \
          "r"((b)[0]), "r"((b)[1]))

__device__ __forceinline__ float fast_exp(float x) {
    float t = fmaxf(x * 1.4426950408889634f, -120.0f);
    float r = rintf(t);
    float f = t - r;
    float p = 1.5403530e-4f;
    p = fmaf(p, f, 1.3333558e-3f);
    p = fmaf(p, f, 9.6181291e-3f);
    p = fmaf(p, f, 5.5504109e-2f);
    p = fmaf(p, f, 2.4022651e-1f);
    p = fmaf(p, f, 6.9314718e-1f);
    p = fmaf(p, f, 1.0f);
    return __int_as_float(__float_as_int(p) + ((int)r << 23));
}

// monotone u32 mapping of float bits (handles negatives)
__device__ __forceinline__ uint32_t fmono(float x) {
    uint32_t f = __float_as_uint(x);
    return f ^ (uint32_t)(((int)f >> 31) | 0x80000000);
}
__device__ __forceinline__ float fmono_inv(uint32_t m) {
    uint32_t f = (m & 0x80000000u) ? (m ^ 0x80000000u) : ~m;
    return __uint_as_float(f);
}

__global__ void k_zero_colsum() {
    int i = blockIdx.x * 256 + threadIdx.x;
    if (i < BB * NN) g_colsum[i] = 0.0f;
}

// ---------------------------------------------------------------------------
// GEMM (exact R7 version — fp32 smem tiles, in-register 3xTF32 split).
// CTA: 128x128, 256 threads (2m x 4n warps of 64x32), K-chunk 32, dbl buffer.
// ---------------------------------------------------------------------------
#define PADW 132
#define TILE_F (32 * PADW)
#define STAGE_F (2 * TILE_F)

__global__ __launch_bounds__(256, 1) void k_gemm_mma(const float* __restrict__ A0,
                                                     const float* __restrict__ B0) {
    extern __shared__ float sm[];
    const int b = blockIdx.z;
    const int m0 = blockIdx.y * 128;
    const int n0 = blockIdx.x * 128;
    const float* A  = A0 + (size_t)b * DD * NN;
    const float* Bt = B0 + (size_t)b * DD * NN;

    const int tid = threadIdx.x;
    const int lane = tid & 31;
    const int wid = tid >> 5;
    const int wm = wid & 1;
    const int wn = wid >> 1;

    float acc[4][4][4];
#pragma unroll
    for (int i = 0; i < 4; i++)
#pragma unroll
        for (int j = 0; j < 4; j++)
#pragma unroll
            for (int q = 0; q < 4; q++) acc[i][j][q] = 0.0f;

    auto load_stage = [&](int kt, int s) {
        float* dstA = sm + s * STAGE_F;
        float* dstB = dstA + TILE_F;
#pragma unroll
        for (int i = 0; i < 8; i++) {
            int u = tid + i * 256;
            int k = (u & 1023) >> 5;
            int c = u & 31;
            if (u < 1024)
                cp16(smem_u32(dstA + k * PADW + c * 4),
                     A + (size_t)(kt * 32 + k) * NN + m0 + c * 4);
            else
                cp16(smem_u32(dstB + k * PADW + c * 4),
                     Bt + (size_t)(kt * 32 + k) * NN + n0 + c * 4);
        }
        CP_COMMIT();
    };

    load_stage(0, 0);

    for (int kt = 0; kt < 16; kt++) {
        if (kt + 1 < 16) {
            load_stage(kt + 1, (kt + 1) & 1);
            asm volatile("cp.async.wait_group 1;" ::: "memory");
        } else {
            asm volatile("cp.async.wait_group 0;" ::: "memory");
        }
        __syncthreads();

        const float* As = sm + (kt & 1) * STAGE_F;
        const float* Bs = As + TILE_F;

#pragma unroll
        for (int kk = 0; kk < 4; kk++) {
            const int kb = kk * 8 + (lane & 3);
            uint32_t a1[4][4], a2[4][4], b1[4][2], b2[4][2];
#pragma unroll
            for (int mt = 0; mt < 4; mt++) {
                int m = wm * 64 + mt * 16 + (lane >> 2);
                float v0 = As[kb * PADW + m];
                float v1 = As[kb * PADW + m + 8];
                float v2 = As[(kb + 4) * PADW + m];
                float v3 = As[(kb + 4) * PADW + m + 8];
                split_tf32(v0, a1[mt][0], a2[mt][0]);
                split_tf32(v1, a1[mt][1], a2[mt][1]);
                split_tf32(v2, a1[mt][2], a2[mt][2]);
                split_tf32(v3, a1[mt][3], a2[mt][3]);
            }
#pragma unroll
            for (int nt = 0; nt < 4; nt++) {
                int n = wn * 32 + nt * 8 + (lane >> 2);
                float v0 = Bs[kb * PADW + n];
                float v1 = Bs[(kb + 4) * PADW + n];
                split_tf32(v0, b1[nt][0], b2[nt][0]);
                split_tf32(v1, b1[nt][1], b2[nt][1]);
            }
#pragma unroll
            for (int mt = 0; mt < 4; mt++)
#pragma unroll
                for (int nt = 0; nt < 4; nt++) {
                    MMA8(acc[mt][nt], a1[mt], b1[nt]);
                    MMA8(acc[mt][nt], a1[mt], b2[nt]);
                    MMA8(acc[mt][nt], a2[mt], b1[nt]);
                }
        }
        __syncthreads();
    }

    const float scl = 0.04419417382415922f;   // 1/sqrt(512)
    float* C = g_logits + (size_t)b * NN * NN;
#pragma unroll
    for (int mt = 0; mt < 4; mt++) {
        int row = m0 + wm * 64 + mt * 16 + (lane >> 2);
#pragma unroll
        for (int nt = 0; nt < 4; nt++) {
            int col = n0 + wn * 32 + nt * 8 + 2 * (lane & 3);
            float2 lo = make_float2(acc[mt][nt][0] * scl, acc[mt][nt][1] * scl);
            float2 hi = make_float2(acc[mt][nt][2] * scl, acc[mt][nt][3] * scl);
            *(float2*)(C + (size_t)row * NN + col) = lo;
            *(float2*)(C + (size_t)(row + 8) * NN + col) = hi;
        }
    }
}

// ---------------------------------------------------------------------------
// Softmax pass: per row — ONE u64 argmax (max + argmax col), exp-sum, colsum.
// Stores (bm, 1/Z, argmax col). NO top-16 extraction. 3 barriers per row.
// ---------------------------------------------------------------------------
__global__ __launch_bounds__(256) void k_softmax_top() {
    const int b = blockIdx.y;
    const int row0 = blockIdx.x * 32;
    const int tid = threadIdx.x;
    const int lane = tid & 31;
    const int wid = tid >> 5;

    __shared__ float colAcc[NN];
    __shared__ float s_red[8];
    __shared__ u64 s_k[8];

    for (int i = tid; i < NN; i += 256) colAcc[i] = 0.0f;
    __syncthreads();

    for (int r = 0; r < 32; r++) {
        const int row = row0 + r;
        const float* L = g_logits + ((size_t)b * NN + row) * NN;
        float v[8];
#pragma unroll
        for (int k = 0; k < 8; k++) v[k] = L[tid + k * 256];

        // single u64 argmax: key = (mono(val) << 32) | ~col  (tie -> smaller col)
        u64 best = 0ull;
#pragma unroll
        for (int k = 0; k < 8; k++) {
            unsigned col = (unsigned)tid + (unsigned)k * 256u;
            u64 key = ((u64)fmono(v[k]) << 32) | (u64)(0xFFFFFFFFu - col);
            if (key > best) best = key;
        }
#pragma unroll
        for (int off = 16; off; off >>= 1) {
            u64 o = __shfl_xor_sync(0xFFFFFFFFu, best, off);
            if (o > best) best = o;
        }
        if (lane == 0) s_k[wid] = best;
        __syncthreads();
        u64 g = s_k[0];
#pragma unroll
        for (int w = 1; w < 8; w++) if (s_k[w] > g) g = s_k[w];
        float bm = fmono_inv((uint32_t)(g >> 32));
        unsigned acol = 0xFFFFFFFFu - (unsigned)(g & 0xFFFFFFFFu);

        float sum = 0.0f;
#pragma unroll
        for (int k = 0; k < 8; k++) { v[k] = fast_exp(v[k] - bm); sum += v[k]; }
#pragma unroll
        for (int off = 16; off; off >>= 1)
            sum += __shfl_xor_sync(0xFFFFFFFFu, sum, off);
        if (lane == 0) s_red[wid] = sum;
        __syncthreads();
        float Z = 0.0f;
#pragma unroll
        for (int w = 0; w < 8; w++) Z += s_red[w];
        float inv = 1.0f / Z;
#pragma unroll
        for (int k = 0; k < 8; k++) colAcc[tid + k * 256] += v[k] * inv;

        if (tid == 0) {
            g_bm[b * NN + row] = bm;
            g_inv[b * NN + row] = inv;
            g_t1col[b * NN + row] = (int)acol;
        }
        __syncthreads();   // protect s_k / s_red for next row
    }

    for (int i = tid; i < NN; i += 256)
        atomicAdd(&g_colsum[b * NN + i], colAcc[i]);
}

// ---------------------------------------------------------------------------
// Tail: greedy matching with lazy row rescans + Kabsch (fp32) + translation.
// Candidate invariant: curk[r] = best unsuppressed (score, col) of row r.
// Init from top-1 (score = 1/Z exactly). On suppression of c*, only rows whose
// candidate col == c* rescan their logits row.
// ---------------------------------------------------------------------------
__global__ __launch_bounds__(256) void k_match_tail(const float* __restrict__ src,
                                                    const float* __restrict__ tgt,
                                                    float* __restrict__ out) {
    const int b = blockIdx.x;
    const int tid = threadIdx.x;
    const int lane = tid & 31;
    const int wid = tid >> 5;

    __shared__ u64 curk[NN];                 // 16 KB
    __shared__ unsigned char usedc[NN];
    __shared__ u64 wred[8];
    __shared__ float sredf[8];
    __shared__ float sums[6];
    __shared__ int selR[NSAMP], selC[NSAMP];
    __shared__ int nfix;
    __shared__ int fixlist[NN];              // 8 KB, worst-case safe

    // sums: src point sum, tgt weighted by colsum
    float a[6] = {0, 0, 0, 0, 0, 0};
    for (int n = tid; n < NN; n += 256) {
        const float* sp = src + ((size_t)b * NN + n) * 3;
        a[0] += sp[0]; a[1] += sp[1]; a[2] += sp[2];
        float w = g_colsum[b * NN + n];
        const float* tp = tgt + ((size_t)b * NN + n) * 3;
        a[3] += tp[0] * w; a[4] += tp[1] * w; a[5] += tp[2] * w;
    }
#pragma unroll
    for (int q = 0; q < 6; q++) {
        float v = a[q];
#pragma unroll
        for (int off = 16; off; off >>= 1) v += __shfl_xor_sync(0xFFFFFFFFu, v, off);
        if (lane == 0) sredf[wid] = v;
        __syncthreads();
        if (tid == 0) {
            float s = 0;
#pragma unroll
            for (int w = 0; w < 8; w++) s += sredf[w];
            sums[q] = s;
        }
        __syncthreads();
    }

    // candidate init: top-1 of each row; score = 1/Z exactly
    for (int r = tid; r < NN; r += 256) {
        usedc[r] = 0;
        float sc = g_inv[b * NN + r];
        int c = g_t1col[b * NN + r];
        curk[r] = ((u64)__float_as_uint(sc) << 32) | ((u64)(2047 - r) << 11) | (u64)c;
    }
    __syncthreads();

    for (int it = 0; it < NSAMP; it++) {
        // block argmax over candidates
        u64 best = 0ull;
#pragma unroll
        for (int k = 0; k < 8; k++) {
            u64 x = curk[tid + k * 256];
            if (x > best) best = x;
        }
#pragma unroll
        for (int off = 16; off; off >>= 1) {
            u64 o = __shfl_xor_sync(0xFFFFFFFFu, best, off);
            if (o > best) best = o;
        }
        if (lane == 0) wred[wid] = best;
        __syncthreads();
        if (tid == 0) {
            u64 g = wred[0];
#pragma unroll
            for (int w = 1; w < 8; w++) if (wred[w] > g) g = wred[w];
            int r = 2047 - (int)((g >> 11) & 0x7FF);
            int c = (int)(g & 0x7FF);
            selR[it] = r; selC[it] = c;
            usedc[c] = 1;
            curk[r] = 0ull;
            nfix = 0;
        }
        __syncthreads();
        const int cstar = selC[it];

        // collect rows whose candidate was suppressed
#pragma unroll
        for (int k = 0; k < 8; k++) {
            int r = tid + k * 256;
            u64 x = curk[r];
            if (x && (int)(x & 0x7FF) == cstar)
                fixlist[atomicAdd(&nfix, 1)] = r;
        }
        __syncthreads();
        const int nf = nfix;

        // block-wide rescan for each affected row
        for (int f = 0; f < nf; f++) {
            const int row = fixlist[f];
            const float* L = g_logits + ((size_t)b * NN + row) * NN;
            const float bmv = g_bm[b * NN + row];
            const float invv = g_inv[b * NN + row];
            u64 rb = 0ull;
#pragma unroll
            for (int k = 0; k < 8; k++) {
                int c = tid + k * 256;
                if (usedc[c]) continue;
                float s = fast_exp(L[c] - bmv) * invv;
                u64 key = ((u64)__float_as_uint(s) << 32) | (u64)(2047 - c);
                if (key > rb) rb = key;
            }
#pragma unroll
            for (int off = 16; off; off >>= 1) {
                u64 o = __shfl_xor_sync(0xFFFFFFFFu, rb, off);
                if (o > rb) rb = o;
            }
            if (lane == 0) wred[wid] = rb;
            __syncthreads();
            if (tid == 0) {
                u64 G = wred[0];
#pragma unroll
                for (int w = 1; w < 8; w++) if (wred[w] > G) G = wred[w];
                int c2 = 2047 - (int)(G & 0xFFFFFFFFu);
                curk[row] = (G & 0xFFFFFFFF00000000ull) |
                            ((u64)(2047 - row) << 11) | (u64)c2;
            }
            __syncthreads();
        }
    }

    if (tid != 0) return;

    // ---- Kabsch (fp32 Jacobi) ----
    float sp[NSAMP][3], tp[NSAMP][3];
    float ms[3] = {0, 0, 0}, mt[3] = {0, 0, 0};
    for (int s = 0; s < NSAMP; s++) {
        const float* ps = src + ((size_t)b * NN + selR[s]) * 3;
        const float* pt = tgt + ((size_t)b * NN + selC[s]) * 3;
        for (int i = 0; i < 3; i++) {
            sp[s][i] = ps[i]; ms[i] += sp[s][i];
            tp[s][i] = pt[i]; mt[i] += tp[s][i];
        }
    }
    for (int i = 0; i < 3; i++) { ms[i] *= (1.0f / NSAMP); mt[i] *= (1.0f / NSAMP); }

    float Hm[3][3] = {{0,0,0},{0,0,0},{0,0,0}};
    for (int s = 0; s < NSAMP; s++)
        for (int i = 0; i < 3; i++)
            for (int j = 0; j < 3; j++)
                Hm[i][j] += (sp[s][i] - ms[i]) * (tp[s][j] - mt[j]);

    float Aq[3][3];
    for (int i = 0; i < 3; i++)
        for (int j = 0; j < 3; j++) {
            float acc = 0;
            for (int k = 0; k < 3; k++) acc += Hm[k][i] * Hm[k][j];
            Aq[i][j] = acc;
        }
    float Vv[3][3] = {{1,0,0},{0,1,0},{0,0,1}};
    const int prs[3][2] = {{0,1},{0,2},{1,2}};
    for (int rot = 0; rot < 24; rot++) {
        int p = prs[rot % 3][0], q = prs[rot % 3][1];
        float apq = Aq[p][q];
        if (fabsf(apq) < 1e-30f) continue;
        float theta = (Aq[q][q] - Aq[p][p]) / (2.0f * apq);
        float tt = (theta >= 0 ? 1.0f : -1.0f) / (fabsf(theta) + sqrtf(theta * theta + 1.0f));
        float c = rsqrtf(tt * tt + 1.0f);
        float s = tt * c;
        for (int k = 0; k < 3; k++) {
            float akp = Aq[k][p], akq = Aq[k][q];
            Aq[k][p] = c * akp - s * akq;
            Aq[k][q] = s * akp + c * akq;
        }
        for (int k = 0; k < 3; k++) {
            float apk = Aq[p][k], aqk = Aq[q][k];
            Aq[p][k] = c * apk - s * aqk;
            Aq[q][k] = s * apk + c * aqk;
        }
        for (int k = 0; k < 3; k++) {
            float vkp = Vv[k][p], vkq = Vv[k][q];
            Vv[k][p] = c * vkp - s * vkq;
            Vv[k][q] = s * vkp + c * vkq;
        }
    }
    float lam[3] = {Aq[0][0], Aq[1][1], Aq[2][2]};
    int ord[3] = {0, 1, 2};
    for (int i = 0; i < 2; i++)
        for (int j = i + 1; j < 3; j++)
            if (lam[ord[j]] > lam[ord[i]]) { int t0 = ord[i]; ord[i] = ord[j]; ord[j] = t0; }

    float Vs[3][3], U[3][3];
    for (int i = 0; i < 3; i++) {
        float sg = sqrtf(fmaxf(lam[ord[i]], 1e-30f));
        for (int k = 0; k < 3; k++) Vs[k][i] = Vv[k][ord[i]];
        for (int k = 0; k < 3; k++) {
            float acc = 0;
            for (int j = 0; j < 3; j++) acc += Hm[k][j] * Vs[j][i];
            U[k][i] = acc / sg;
        }
    }
    float Rr[3][3];
    for (int i = 0; i < 3; i++)
        for (int j = 0; j < 3; j++) {
            float acc = 0;
            for (int k = 0; k < 3; k++) acc += Vs[i][k] * U[j][k];
            Rr[i][j] = acc;
        }
    float det = Rr[0][0] * (Rr[1][1] * Rr[2][2] - Rr[1][2] * Rr[2][1])
              - Rr[0][1] * (Rr[1][0] * Rr[2][2] - Rr[1][2] * Rr[2][0])
              + Rr[0][2] * (Rr[1][0] * Rr[2][1] - Rr[1][1] * Rr[2][0]);
    if (det < 0) {
        for (int k = 0; k < 3; k++) Vs[k][2] = -Vs[k][2];
        for (int i = 0; i < 3; i++)
            for (int j = 0; j < 3; j++) {
                float acc = 0;
                for (int k = 0; k < 3; k++) acc += Vs[i][k] * U[j][k];
                Rr[i][j] = acc;
            }
    }

    float msrc[3] = {sums[0] / (float)NN, sums[1] / (float)NN, sums[2] / (float)NN};
    float corr[3] = {sums[3] / (float)NN, sums[4] / (float)NN, sums[5] / (float)NN};
    for (int i = 0; i < 3; i++)
        for (int j = 0; j < 3; j++)
            out[b * 9 + i * 3 + j] = Rr[i][j];
    for (int i = 0; i < 3; i++) {
        float ti = -(Rr[i][0] * msrc[0] + Rr[i][1] * msrc[1] + Rr[i][2] * msrc[2]) + corr[i];
        out[BB * 9 + b * 3 + i] = ti;
    }
}

// ---------------------------------------------------------------------------
extern "C" void kernel_launch(void* const* d_in, const int* in_sizes, int n_in,
                              void* d_out, int out_size) {
    const float* se  = (const float*)d_in[0];
    const float* te  = (const float*)d_in[1];
    const float* src = (const float*)d_in[2];
    const float* tgt = (const float*)d_in[3];
    float* out = (float*)d_out;

    const int smem_bytes = 2 * STAGE_F * (int)sizeof(float);   // 67584
    cudaFuncSetAttribute(k_gemm_mma, cudaFuncAttributeMaxDynamicSharedMemorySize,
                         smem_bytes);

    k_zero_colsum<<<(BB * NN + 255) / 256, 256>>>();
    k_gemm_mma<<<dim3(16, 16, BB), 256, smem_bytes>>>(se, te);
    k_softmax_top<<<dim3(NN / 32, BB), 256>>>();
    k_match_tail<<<BB, 256>>>(src, tgt, out);
}

// round 14
// speedup vs baseline: 1.7119x; 1.0355x over previous
#include <cuda_runtime.h>
#include <stdint.h>

#define BB    16
#define DD    512
#define NN    2048
#define NSAMP 15
typedef unsigned long long u64;

// ---------------- scratch (__device__ globals; no allocation) ----------------
__device__ float g_logits[(size_t)BB * NN * NN];   // 256 MB
__device__ float g_colsum[BB * NN];
__device__ float g_bm[BB * NN];      // per-row max logit
__device__ float g_inv[BB * NN];     // per-row 1/Z
__device__ int   g_t1col[BB * NN];   // per-row argmax col

// ---------------- helpers ----------------
__device__ __forceinline__ uint32_t smem_u32(const void* p) {
    uint32_t a;
    asm("{ .reg .u64 t; cvta.to.shared.u64 t, %1; cvt.u32.u64 %0, t; }" : "=r"(a) : "l"(p));
    return a;
}
__device__ __forceinline__ void cp16(uint32_t dst, const void* src) {
    asm volatile("cp.async.cg.shared.global [%0], [%1], 16;" :: "r"(dst), "l"(src));
}
#define CP_COMMIT() asm volatile("cp.async.commit_group;" ::: "memory")

__device__ __forceinline__ void split_tf32(float x, uint32_t& hi, uint32_t& lo) {
    uint32_t h, l;
    asm("cvt.rna.tf32.f32 %0, %1;" : "=r"(h) : "f"(x));
    float r = x - __uint_as_float(h);
    asm("cvt.rna.tf32.f32 %0, %1;" : "=r"(l) : "f"(r));
    hi = h; lo = l;
}

#define MMA8(d, a, b)                                                              \
    asm volatile("mma.sync.aligned.m16n8k8.row.col.f32.tf32.tf32.f32 "             \
        "{%0,%1,%2,%3}, {%4,%5,%6,%7}, {%8,%9}, {%0,%1,%2,%3};"                    \
        : "+f"((d)[0]), "+f"((d)[1]), "+f"((d)[2]), "+f"((d)[3])                   \
        : "r"((a)[0]), "r"((a)[1]), "r"((a)[2]), "r"((a)[3]),                      \
          "r"((b)[0]), "r"((b)[1]))

__device__ __forceinline__ float fast_exp(float x) {
    float t = fmaxf(x * 1.4426950408889634f, -120.0f);
    float r = rintf(t);
    float f = t - r;
    float p = 1.5403530e-4f;
    p = fmaf(p, f, 1.3333558e-3f);
    p = fmaf(p, f, 9.6181291e-3f);
    p = fmaf(p, f, 5.5504109e-2f);
    p = fmaf(p, f, 2.4022651e-1f);
    p = fmaf(p, f, 6.9314718e-1f);
    p = fmaf(p, f, 1.0f);
    return __int_as_float(__float_as_int(p) + ((int)r << 23));
}

// monotone u32 mapping of float bits (handles negatives)
__device__ __forceinline__ uint32_t fmono(float x) {
    uint32_t f = __float_as_uint(x);
    return f ^ (uint32_t)(((int)f >> 31) | 0x80000000);
}
__device__ __forceinline__ float fmono_inv(uint32_t m) {
    uint32_t f = (m & 0x80000000u) ? (m ^ 0x80000000u) : ~m;
    return __uint_as_float(f);
}

__global__ void k_zero_colsum() {
    int i = blockIdx.x * 256 + threadIdx.x;
    if (i < BB * NN) g_colsum[i] = 0.0f;
}

// ---------------------------------------------------------------------------
// GEMM: 3xTF32 via mma.sync, fp32 smem staging, in-register split.
// CTA tile 256(m) x 128(n), 256 threads = 8 warps (4m x 2n) of 64x64.
// K-chunk 32, double-buffered cp.async. 2.33 issue-slots per MMA (was 3.0).
// ---------------------------------------------------------------------------
#define PADA 260
#define PADB 132
#define A_TILE_F (32 * PADA)
#define B_TILE_F (32 * PADB)
#define STAGE_F  (A_TILE_F + B_TILE_F)

__global__ __launch_bounds__(256, 1) void k_gemm_mma(const float* __restrict__ A0,
                                                     const float* __restrict__ B0) {
    extern __shared__ float sm[];
    const int b = blockIdx.z;
    const int m0 = blockIdx.y * 256;
    const int n0 = blockIdx.x * 128;
    const float* A  = A0 + (size_t)b * DD * NN;
    const float* Bt = B0 + (size_t)b * DD * NN;

    const int tid = threadIdx.x;
    const int lane = tid & 31;
    const int wid = tid >> 5;
    const int wm = wid & 3;     // 4 m-warps of 64
    const int wn = wid >> 2;    // 2 n-warps of 64

    float acc[4][8][4];
#pragma unroll
    for (int i = 0; i < 4; i++)
#pragma unroll
        for (int j = 0; j < 8; j++)
#pragma unroll
            for (int q = 0; q < 4; q++) acc[i][j][q] = 0.0f;

    auto load_stage = [&](int kt, int s) {
        float* dA = sm + (size_t)s * STAGE_F;
        float* dB = dA + A_TILE_F;
#pragma unroll
        for (int i = 0; i < 8; i++) {          // A: 2048 16B chunks
            int u = tid + i * 256;
            int k = u >> 6, c = u & 63;
            cp16(smem_u32(dA + k * PADA + c * 4),
                 A + (size_t)(kt * 32 + k) * NN + m0 + c * 4);
        }
#pragma unroll
        for (int i = 0; i < 4; i++) {          // B: 1024 16B chunks
            int u = tid + i * 256;
            int k = u >> 5, c = u & 31;
            cp16(smem_u32(dB + k * PADB + c * 4),
                 Bt + (size_t)(kt * 32 + k) * NN + n0 + c * 4);
        }
        CP_COMMIT();
    };

    load_stage(0, 0);

    for (int kt = 0; kt < 16; kt++) {
        if (kt + 1 < 16) {
            load_stage(kt + 1, (kt + 1) & 1);
            asm volatile("cp.async.wait_group 1;" ::: "memory");
        } else {
            asm volatile("cp.async.wait_group 0;" ::: "memory");
        }
        __syncthreads();

        const float* As = sm + (size_t)(kt & 1) * STAGE_F;
        const float* Bs = As + A_TILE_F;

#pragma unroll
        for (int kk = 0; kk < 4; kk++) {
            const int kb = kk * 8 + (lane & 3);
            uint32_t a1[4][4], a2[4][4], b1[8][2], b2[8][2];
#pragma unroll
            for (int mt = 0; mt < 4; mt++) {
                int m = wm * 64 + mt * 16 + (lane >> 2);
                float v0 = As[kb * PADA + m];
                float v1 = As[kb * PADA + m + 8];
                float v2 = As[(kb + 4) * PADA + m];
                float v3 = As[(kb + 4) * PADA + m + 8];
                split_tf32(v0, a1[mt][0], a2[mt][0]);
                split_tf32(v1, a1[mt][1], a2[mt][1]);
                split_tf32(v2, a1[mt][2], a2[mt][2]);
                split_tf32(v3, a1[mt][3], a2[mt][3]);
            }
#pragma unroll
            for (int nt = 0; nt < 8; nt++) {
                int n = wn * 64 + nt * 8 + (lane >> 2);
                float v0 = Bs[kb * PADB + n];
                float v1 = Bs[(kb + 4) * PADB + n];
                split_tf32(v0, b1[nt][0], b2[nt][0]);
                split_tf32(v1, b1[nt][1], b2[nt][1]);
            }
#pragma unroll
            for (int mt = 0; mt < 4; mt++)
#pragma unroll
                for (int nt = 0; nt < 8; nt++) {
                    MMA8(acc[mt][nt], a1[mt], b1[nt]);
                    MMA8(acc[mt][nt], a1[mt], b2[nt]);
                    MMA8(acc[mt][nt], a2[mt], b1[nt]);
                }
        }
        __syncthreads();
    }

    const float scl = 0.04419417382415922f;   // 1/sqrt(512)
    float* C = g_logits + (size_t)b * NN * NN;
#pragma unroll
    for (int mt = 0; mt < 4; mt++) {
        int row = m0 + wm * 64 + mt * 16 + (lane >> 2);
#pragma unroll
        for (int nt = 0; nt < 8; nt++) {
            int col = n0 + wn * 64 + nt * 8 + 2 * (lane & 3);
            float2 lo = make_float2(acc[mt][nt][0] * scl, acc[mt][nt][1] * scl);
            float2 hi = make_float2(acc[mt][nt][2] * scl, acc[mt][nt][3] * scl);
            *(float2*)(C + (size_t)row * NN + col) = lo;
            *(float2*)(C + (size_t)(row + 8) * NN + col) = hi;
        }
    }
}

// ---------------------------------------------------------------------------
// Softmax pass: per row — ONE u64 argmax, exp-sum, colsum. (R13, unchanged)
// ---------------------------------------------------------------------------
__global__ __launch_bounds__(256) void k_softmax_top() {
    const int b = blockIdx.y;
    const int row0 = blockIdx.x * 32;
    const int tid = threadIdx.x;
    const int lane = tid & 31;
    const int wid = tid >> 5;

    __shared__ float colAcc[NN];
    __shared__ float s_red[8];
    __shared__ u64 s_k[8];

    for (int i = tid; i < NN; i += 256) colAcc[i] = 0.0f;
    __syncthreads();

    for (int r = 0; r < 32; r++) {
        const int row = row0 + r;
        const float* L = g_logits + ((size_t)b * NN + row) * NN;
        float v[8];
#pragma unroll
        for (int k = 0; k < 8; k++) v[k] = L[tid + k * 256];

        u64 best = 0ull;
#pragma unroll
        for (int k = 0; k < 8; k++) {
            unsigned col = (unsigned)tid + (unsigned)k * 256u;
            u64 key = ((u64)fmono(v[k]) << 32) | (u64)(0xFFFFFFFFu - col);
            if (key > best) best = key;
        }
#pragma unroll
        for (int off = 16; off; off >>= 1) {
            u64 o = __shfl_xor_sync(0xFFFFFFFFu, best, off);
            if (o > best) best = o;
        }
        if (lane == 0) s_k[wid] = best;
        __syncthreads();
        u64 g = s_k[0];
#pragma unroll
        for (int w = 1; w < 8; w++) if (s_k[w] > g) g = s_k[w];
        float bm = fmono_inv((uint32_t)(g >> 32));
        unsigned acol = 0xFFFFFFFFu - (unsigned)(g & 0xFFFFFFFFu);

        float sum = 0.0f;
#pragma unroll
        for (int k = 0; k < 8; k++) { v[k] = fast_exp(v[k] - bm); sum += v[k]; }
#pragma unroll
        for (int off = 16; off; off >>= 1)
            sum += __shfl_xor_sync(0xFFFFFFFFu, sum, off);
        if (lane == 0) s_red[wid] = sum;
        __syncthreads();
        float Z = 0.0f;
#pragma unroll
        for (int w = 0; w < 8; w++) Z += s_red[w];
        float inv = 1.0f / Z;
#pragma unroll
        for (int k = 0; k < 8; k++) colAcc[tid + k * 256] += v[k] * inv;

        if (tid == 0) {
            g_bm[b * NN + row] = bm;
            g_inv[b * NN + row] = inv;
            g_t1col[b * NN + row] = (int)acol;
        }
        __syncthreads();
    }

    for (int i = tid; i < NN; i += 256)
        atomicAdd(&g_colsum[b * NN + i], colAcc[i]);
}

// ---------------------------------------------------------------------------
// Tail: greedy matching with lazy row rescans + Kabsch (fp32). (R13, unchanged)
// ---------------------------------------------------------------------------
__global__ __launch_bounds__(256) void k_match_tail(const float* __restrict__ src,
                                                    const float* __restrict__ tgt,
                                                    float* __restrict__ out) {
    const int b = blockIdx.x;
    const int tid = threadIdx.x;
    const int lane = tid & 31;
    const int wid = tid >> 5;

    __shared__ u64 curk[NN];
    __shared__ unsigned char usedc[NN];
    __shared__ u64 wred[8];
    __shared__ float sredf[8];
    __shared__ float sums[6];
    __shared__ int selR[NSAMP], selC[NSAMP];
    __shared__ int nfix;
    __shared__ int fixlist[NN];

    float a[6] = {0, 0, 0, 0, 0, 0};
    for (int n = tid; n < NN; n += 256) {
        const float* sp = src + ((size_t)b * NN + n) * 3;
        a[0] += sp[0]; a[1] += sp[1]; a[2] += sp[2];
        float w = g_colsum[b * NN + n];
        const float* tp = tgt + ((size_t)b * NN + n) * 3;
        a[3] += tp[0] * w; a[4] += tp[1] * w; a[5] += tp[2] * w;
    }
#pragma unroll
    for (int q = 0; q < 6; q++) {
        float v = a[q];
#pragma unroll
        for (int off = 16; off; off >>= 1) v += __shfl_xor_sync(0xFFFFFFFFu, v, off);
        if (lane == 0) sredf[wid] = v;
        __syncthreads();
        if (tid == 0) {
            float s = 0;
#pragma unroll
            for (int w = 0; w < 8; w++) s += sredf[w];
            sums[q] = s;
        }
        __syncthreads();
    }

    for (int r = tid; r < NN; r += 256) {
        usedc[r] = 0;
        float sc = g_inv[b * NN + r];
        int c = g_t1col[b * NN + r];
        curk[r] = ((u64)__float_as_uint(sc) << 32) | ((u64)(2047 - r) << 11) | (u64)c;
    }
    __syncthreads();

    for (int it = 0; it < NSAMP; it++) {
        u64 best = 0ull;
#pragma unroll
        for (int k = 0; k < 8; k++) {
            u64 x = curk[tid + k * 256];
            if (x > best) best = x;
        }
#pragma unroll
        for (int off = 16; off; off >>= 1) {
            u64 o = __shfl_xor_sync(0xFFFFFFFFu, best, off);
            if (o > best) best = o;
        }
        if (lane == 0) wred[wid] = best;
        __syncthreads();
        if (tid == 0) {
            u64 g = wred[0];
#pragma unroll
            for (int w = 1; w < 8; w++) if (wred[w] > g) g = wred[w];
            int r = 2047 - (int)((g >> 11) & 0x7FF);
            int c = (int)(g & 0x7FF);
            selR[it] = r; selC[it] = c;
            usedc[c] = 1;
            curk[r] = 0ull;
            nfix = 0;
        }
        __syncthreads();
        const int cstar = selC[it];

#pragma unroll
        for (int k = 0; k < 8; k++) {
            int r = tid + k * 256;
            u64 x = curk[r];
            if (x && (int)(x & 0x7FF) == cstar)
                fixlist[atomicAdd(&nfix, 1)] = r;
        }
        __syncthreads();
        const int nf = nfix;

        for (int f = 0; f < nf; f++) {
            const int row = fixlist[f];
            const float* L = g_logits + ((size_t)b * NN + row) * NN;
            const float bmv = g_bm[b * NN + row];
            const float invv = g_inv[b * NN + row];
            u64 rb = 0ull;
#pragma unroll
            for (int k = 0; k < 8; k++) {
                int c = tid + k * 256;
                if (usedc[c]) continue;
                float s = fast_exp(L[c] - bmv) * invv;
                u64 key = ((u64)__float_as_uint(s) << 32) | (u64)(2047 - c);
                if (key > rb) rb = key;
            }
#pragma unroll
            for (int off = 16; off; off >>= 1) {
                u64 o = __shfl_xor_sync(0xFFFFFFFFu, rb, off);
                if (o > rb) rb = o;
            }
            if (lane == 0) wred[wid] = rb;
            __syncthreads();
            if (tid == 0) {
                u64 G = wred[0];
#pragma unroll
                for (int w = 1; w < 8; w++) if (wred[w] > G) G = wred[w];
                int c2 = 2047 - (int)(G & 0xFFFFFFFFu);
                curk[row] = (G & 0xFFFFFFFF00000000ull) |
                            ((u64)(2047 - row) << 11) | (u64)c2;
            }
            __syncthreads();
        }
    }

    if (tid != 0) return;

    float sp[NSAMP][3], tp[NSAMP][3];
    float ms[3] = {0, 0, 0}, mt[3] = {0, 0, 0};
    for (int s = 0; s < NSAMP; s++) {
        const float* ps = src + ((size_t)b * NN + selR[s]) * 3;
        const float* pt = tgt + ((size_t)b * NN + selC[s]) * 3;
        for (int i = 0; i < 3; i++) {
            sp[s][i] = ps[i]; ms[i] += sp[s][i];
            tp[s][i] = pt[i]; mt[i] += tp[s][i];
        }
    }
    for (int i = 0; i < 3; i++) { ms[i] *= (1.0f / NSAMP); mt[i] *= (1.0f / NSAMP); }

    float Hm[3][3] = {{0,0,0},{0,0,0},{0,0,0}};
    for (int s = 0; s < NSAMP; s++)
        for (int i = 0; i < 3; i++)
            for (int j = 0; j < 3; j++)
                Hm[i][j] += (sp[s][i] - ms[i]) * (tp[s][j] - mt[j]);

    float Aq[3][3];
    for (int i = 0; i < 3; i++)
        for (int j = 0; j < 3; j++) {
            float acc = 0;
            for (int k = 0; k < 3; k++) acc += Hm[k][i] * Hm[k][j];
            Aq[i][j] = acc;
        }
    float Vv[3][3] = {{1,0,0},{0,1,0},{0,0,1}};
    const int prs[3][2] = {{0,1},{0,2},{1,2}};
    for (int rot = 0; rot < 24; rot++) {
        int p = prs[rot % 3][0], q = prs[rot % 3][1];
        float apq = Aq[p][q];
        if (fabsf(apq) < 1e-30f) continue;
        float theta = (Aq[q][q] - Aq[p][p]) / (2.0f * apq);
        float tt = (theta >= 0 ? 1.0f : -1.0f) / (fabsf(theta) + sqrtf(theta * theta + 1.0f));
        float c = rsqrtf(tt * tt + 1.0f);
        float s = tt * c;
        for (int k = 0; k < 3; k++) {
            float akp = Aq[k][p], akq = Aq[k][q];
            Aq[k][p] = c * akp - s * akq;
            Aq[k][q] = s * akp + c * akq;
        }
        for (int k = 0; k < 3; k++) {
            float apk = Aq[p][k], aqk = Aq[q][k];
            Aq[p][k] = c * apk - s * aqk;
            Aq[q][k] = s * apk + c * aqk;
        }
        for (int k = 0; k < 3; k++) {
            float vkp = Vv[k][p], vkq = Vv[k][q];
            Vv[k][p] = c * vkp - s * vkq;
            Vv[k][q] = s * vkp + c * vkq;
        }
    }
    float lam[3] = {Aq[0][0], Aq[1][1], Aq[2][2]};
    int ord[3] = {0, 1, 2};
    for (int i = 0; i < 2; i++)
        for (int j = i + 1; j < 3; j++)
            if (lam[ord[j]] > lam[ord[i]]) { int t0 = ord[i]; ord[i] = ord[j]; ord[j] = t0; }

    float Vs[3][3], U[3][3];
    for (int i = 0; i < 3; i++) {
        float sg = sqrtf(fmaxf(lam[ord[i]], 1e-30f));
        for (int k = 0; k < 3; k++) Vs[k][i] = Vv[k][ord[i]];
        for (int k = 0; k < 3; k++) {
            float acc = 0;
            for (int j = 0; j < 3; j++) acc += Hm[k][j] * Vs[j][i];
            U[k][i] = acc / sg;
        }
    }
    float Rr[3][3];
    for (int i = 0; i < 3; i++)
        for (int j = 0; j < 3; j++) {
            float acc = 0;
            for (int k = 0; k < 3; k++) acc += Vs[i][k] * U[j][k];
            Rr[i][j] = acc;
        }
    float det = Rr[0][0] * (Rr[1][1] * Rr[2][2] - Rr[1][2] * Rr[2][1])
              - Rr[0][1] * (Rr[1][0] * Rr[2][2] - Rr[1][2] * Rr[2][0])
              + Rr[0][2] * (Rr[1][0] * Rr[2][1] - Rr[1][1] * Rr[2][0]);
    if (det < 0) {
        for (int k = 0; k < 3; k++) Vs[k][2] = -Vs[k][2];
        for (int i = 0; i < 3; i++)
            for (int j = 0; j < 3; j++) {
                float acc = 0;
                for (int k = 0; k < 3; k++) acc += Vs[i][k] * U[j][k];
                Rr[i][j] = acc;
            }
    }

    float msrc[3] = {sums[0] / (float)NN, sums[1] / (float)NN, sums[2] / (float)NN};
    float corr[3] = {sums[3] / (float)NN, sums[4] / (float)NN, sums[5] / (float)NN};
    for (int i = 0; i < 3; i++)
        for (int j = 0; j < 3; j++)
            out[b * 9 + i * 3 + j] = Rr[i][j];
    for (int i = 0; i < 3; i++) {
        float ti = -(Rr[i][0] * msrc[0] + Rr[i][1] * msrc[1] + Rr[i][2] * msrc[2]) + corr[i];
        out[BB * 9 + b * 3 + i] = ti;
    }
}

// ---------------------------------------------------------------------------
extern "C" void kernel_launch(void* const* d_in, const int* in_sizes, int n_in,
                              void* d_out, int out_size) {
    const float* se  = (const float*)d_in[0];
    const float* te  = (const float*)d_in[1];
    const float* src = (const float*)d_in[2];
    const float* tgt = (const float*)d_in[3];
    float* out = (float*)d_out;

    const int smem_bytes = 2 * STAGE_F * (int)sizeof(float);   // 100352
    cudaFuncSetAttribute(k_gemm_mma, cudaFuncAttributeMaxDynamicSharedMemorySize,
                         smem_bytes);

    k_zero_colsum<<<(BB * NN + 255) / 256, 256>>>();
    k_gemm_mma<<<dim3(16, 8, BB), 256, smem_bytes>>>(se, te);
    k_softmax_top<<<dim3(NN / 32, BB), 256>>>();
    k_match_tail<<<BB, 256>>>(src, tgt, out);
}